// round 11
// baseline (speedup 1.0000x reference)
#include <cuda_runtime.h>

#define NB 4
#define LL 4096
#define ND 8
#define KMAX 64
#define NCODES 256
#define BIGV 65535

// Scratch (no allocations). Counters zero-initialized; each consumer block
// solely owns + resets its counters -> deterministic across graph replays.
__device__ int            g_cnt  [NB * NCODES];          // key counts, 4 KB
__device__ int            g_qcnt [NB * NCODES];          // query counts, 4 KB
__device__ unsigned short g_tmp  [NB * NCODES * KMAX];   // key buckets, 128 KB
__device__ unsigned short g_qtmp [NB * NCODES * LL];     // query buckets (cap)
__device__ unsigned char  g_codes[NB * LL];              // key codes (overflow)

__device__ __forceinline__ int pack8(float4 a, float4 c) {
    return (a.x > 0.f)        | ((a.y > 0.f) << 1) |
           ((a.z > 0.f) << 2) | ((a.w > 0.f) << 3) |
           ((c.x > 0.f) << 4) | ((c.y > 0.f) << 5) |
           ((c.z > 0.f) << 6) | ((c.w > 0.f) << 7);
}

// K1 (producer): blocks 0..127 scatter keys, 128..255 scatter queries.
__global__ void __launch_bounds__(128)
k_prep(const float* __restrict__ key_up, const float* __restrict__ query_up) {
    int t = (blockIdx.x & 127) * 128 + threadIdx.x;      // item id 0..16383
    if (blockIdx.x < 128) {
        const float4* p = reinterpret_cast<const float4*>(key_up) + t * 2;
        int code = pack8(p[0], p[1]);
        g_codes[t] = (unsigned char)code;
        int cidx = ((t >> 12) << 8) | code;
        int pos = atomicAdd(&g_cnt[cidx], 1);
        if (pos < KMAX) g_tmp[cidx * KMAX + pos] = (unsigned short)(t & (LL - 1));
    } else {
        const float4* p = reinterpret_cast<const float4*>(query_up) + t * 2;
        int code = pack8(p[0], p[1]);
        int cidx = ((t >> 12) << 8) | code;
        int pos = atomicAdd(&g_qcnt[cidx], 1);
        g_qtmp[cidx * LL + pos] = (unsigned short)(t & (LL - 1));
    }
#if defined(__CUDA_ARCH__) && __CUDA_ARCH__ >= 900
    cudaTriggerProgrammaticLaunchCompletion();
#endif
}

// K2 (consumer, PDL): one block per (batch,code). Ramp/prologue overlap K1;
// grid-sync right before touching scattered data. Warp 0 rank-sorts the <=64
// key indices into the padded ascending smem row; all 4 warps then push the
// row to every query in the bucket (256B coalesced stores).
__global__ void __launch_bounds__(128)
k_rank_emit(float* __restrict__ out) {
    __shared__ float row[KMAX];
    int cidx = blockIdx.x;
    int tid  = threadIdx.x;
    int warp = tid >> 5;
    int lane = tid & 31;
    int b    = cidx >> 8;
    int g    = lane >> 3, o = lane & 7;

#if defined(__CUDA_ARCH__) && __CUDA_ARCH__ >= 900
    cudaGridDependencySynchronize();
#endif

    int nq = g_qcnt[cidx];                               // all threads, pre-sync

    if (warp == 0) {
        int n = g_cnt[cidx];
        if (n <= KMAX) {
            int v0 = (lane      < n) ? (int)g_tmp[cidx * KMAX + lane]      : BIGV;
            int v1 = (lane + 32 < n) ? (int)g_tmp[cidx * KMAX + lane + 32] : BIGV;
            int r0 = 0, r1 = 0;
            #pragma unroll
            for (int k = 0; k < 32; k++) {
                int u0 = __shfl_sync(0xffffffffu, v0, k);
                int u1 = __shfl_sync(0xffffffffu, v1, k);
                r0 += (u0 < v0) + (u1 < v0);
                r1 += (u0 < v1) + (u1 < v1);
            }
            int pad = KMAX - n;                          // disjoint targets
            if (lane      < pad) row[lane]      = -1.0f;
            if (lane + 32 < pad) row[lane + 32] = -1.0f;
            if (v0 != BIGV) row[pad + r0] = (float)v0;
            if (v1 != BIGV) row[pad + r1] = (float)v1;
        } else {
            // >64 matches (stat. impossible, guarded): stable ballot scan.
            int bb = cidx >> 8, c = cidx & 255;
            const uchar4* cc = reinterpret_cast<const uchar4*>(g_codes + bb * LL);
            unsigned lt = (1u << lane) - 1u;
            int m = 0;
            for (int r = 0; r < 32 && m < KMAX; r++) {
                uchar4 v = cc[r * 32 + lane];
                unsigned m0 = __ballot_sync(0xffffffffu, v.x == c);
                unsigned m1 = __ballot_sync(0xffffffffu, v.y == c);
                unsigned m2 = __ballot_sync(0xffffffffu, v.z == c);
                unsigned m3 = __ballot_sync(0xffffffffu, v.w == c);
                int p = m + __popc(m0 & lt) + __popc(m1 & lt)
                          + __popc(m2 & lt) + __popc(m3 & lt);
                int j0 = (r * 32 + lane) * 4;
                if (v.x == c) { if (p < KMAX) row[p] = (float)j0;       p++; }
                if (v.y == c) { if (p < KMAX) row[p] = (float)(j0 + 1); p++; }
                if (v.z == c) { if (p < KMAX) row[p] = (float)(j0 + 2); p++; }
                if (v.w == c) { if (p < KMAX) row[p] = (float)(j0 + 3); p++; }
                m += __popc(m0) + __popc(m1) + __popc(m2) + __popc(m3);
            }
        }
        if (lane == 0) g_cnt[cidx] = 0;                  // self-reset
    }
    __syncthreads();                                     // row ready

    const unsigned short* qb = g_qtmp + cidx * LL;
    float4 rv0 = reinterpret_cast<const float4*>(row)[o];     // smem broadcast
    float4 rv1 = reinterpret_cast<const float4*>(row)[o + 8];
    for (int q0 = warp * 4; q0 < nq; q0 += 16) {
        int qq = q0 + g;
        if (qq < nq) {
            int qid = (int)qb[qq];
            float4* dst = reinterpret_cast<float4*>(out)
                          + (size_t)(b * LL + qid) * 16;
            dst[o]     = rv0;
            dst[o + 8] = rv1;
        }
    }
    if (tid == 0) g_qcnt[cidx] = 0;                      // all read nq pre-sync
}

extern "C" void kernel_launch(void* const* d_in, const int* in_sizes, int n_in,
                              void* d_out, int out_size) {
    // Identify inputs by element count (robust to metadata ordering).
    const float* query_up = nullptr;
    const float* key_up   = nullptr;
    for (int i = 0; i < n_in; i++) {
        if (in_sizes[i] == NB * LL * ND) {
            if (!query_up)      query_up = (const float*)d_in[i];
            else if (!key_up)   key_up   = (const float*)d_in[i];
        }
    }
    if (!query_up || !key_up) {
        query_up = (const float*)d_in[0];
        key_up   = (const float*)d_in[1];
    }
    float* out = (float*)d_out;

    k_prep<<<256, 128>>>(key_up, query_up);              // producer

    // Consumer with PDL: overlaps its ramp/prologue with the producer.
    cudaLaunchConfig_t cfg = {};
    cfg.gridDim  = dim3(NB * NCODES, 1, 1);
    cfg.blockDim = dim3(128, 1, 1);
    cfg.dynamicSmemBytes = 0;
    cfg.stream = 0;                                      // capture stream
    cudaLaunchAttribute attr[1];
    attr[0].id = cudaLaunchAttributeProgrammaticStreamSerialization;
    attr[0].val.programmaticStreamSerializationAllowed = 1;
    cfg.attrs = attr;
    cfg.numAttrs = 1;
    cudaError_t e = cudaLaunchKernelEx(&cfg, k_rank_emit, out);
    if (e != cudaSuccess) {                              // safe fallback
        k_rank_emit<<<NB * NCODES, 128>>>(out);
    }
}